// round 5
// baseline (speedup 1.0000x reference)
#include <cuda_runtime.h>
#include <cuda_bf16.h>

// out[row, :] = W[days[row], :] + bias.  131072 rows, D = 1024 fp32.
//
// Persistent-CTA, SM-affine chunking: D is split into 8 chunks of 128 floats.
// Each CTA picks chunk = %smid & 7, so all CTAs resident on one SM gather from
// the SAME 187KB W-slice -> L1D-resident reads (228KB L1, no smem used).
// Rows are handed out by per-chunk atomic counters (4 rows per warp-grab);
// after its own chunk drains, a CTA steals from the other chunks.
// L2/DRAM then carry (almost) only the 537MB streaming write.

static constexpr int D4       = 256;   // 1024 floats / 4
static constexpr int CHUNK4   = 32;    // 128 floats per chunk = 32 float4
static constexpr int NCHUNK   = 8;
static constexpr int GRAB     = 4;     // rows per warp-grab (MLP=4)

__device__ unsigned int g_ctr[NCHUNK];

__global__ void doy_init_ctr()
{
    if (threadIdx.x < NCHUNK) g_ctr[threadIdx.x] = 0;
}

__global__ void __launch_bounds__(512, 3)
doy_persistent_kernel(const int* __restrict__ days,
                      const float4* __restrict__ W4,
                      const float4* __restrict__ b4,
                      float4* __restrict__ out4,
                      unsigned int n_rows)
{
    unsigned int smid;
    asm("mov.u32 %0, %%smid;" : "=r"(smid));
    const int my_chunk = smid & (NCHUNK - 1);
    const int lane = threadIdx.x & 31;

#pragma unroll 1
    for (int cc = 0; cc < NCHUNK; ++cc) {
        const int ch  = (my_chunk + cc) & (NCHUNK - 1);
        const int cb4 = ch * CHUNK4;

        const float4 bv = __ldg(b4 + cb4 + lane);

        while (true) {
            unsigned int base;
            if (lane == 0) base = atomicAdd(&g_ctr[ch], GRAB);
            base = __shfl_sync(0xffffffffu, base, 0);
            if (base >= n_rows) break;

            // n_rows divisible by GRAB -> no bounds check per row
            const int d0 = __ldg(days + base + 0);
            const int d1 = __ldg(days + base + 1);
            const int d2 = __ldg(days + base + 2);
            const int d3 = __ldg(days + base + 3);

            float4 w0 = __ldg(W4 + (size_t)d0 * D4 + cb4 + lane);
            float4 w1 = __ldg(W4 + (size_t)d1 * D4 + cb4 + lane);
            float4 w2 = __ldg(W4 + (size_t)d2 * D4 + cb4 + lane);
            float4 w3 = __ldg(W4 + (size_t)d3 * D4 + cb4 + lane);

            w0.x += bv.x; w0.y += bv.y; w0.z += bv.z; w0.w += bv.w;
            w1.x += bv.x; w1.y += bv.y; w1.z += bv.z; w1.w += bv.w;
            w2.x += bv.x; w2.y += bv.y; w2.z += bv.z; w2.w += bv.w;
            w3.x += bv.x; w3.y += bv.y; w3.z += bv.z; w3.w += bv.w;

            float4* op = out4 + (size_t)base * D4 + cb4 + lane;
            __stcs(op + 0 * D4, w0);
            __stcs(op + 1 * D4, w1);
            __stcs(op + 2 * D4, w2);
            __stcs(op + 3 * D4, w3);
        }
    }
}

extern "C" void kernel_launch(void* const* d_in, const int* in_sizes, int n_in,
                              void* d_out, int out_size)
{
    const int*    days = (const int*)d_in[0];
    const float4* W4   = (const float4*)d_in[1];
    const float4* b4   = (const float4*)d_in[2];
    float4*       out4 = (float4*)d_out;

    const unsigned int n_rows = (unsigned int)in_sizes[0];   // 131072

    doy_init_ctr<<<1, 32>>>();
    // 148 SMs * 3 CTAs of 512 threads (persistent, work-stealing)
    doy_persistent_kernel<<<444, 512>>>(days, W4, b4, out4, n_rows);
}

// round 6
// speedup vs baseline: 2.2817x; 2.2817x over previous
#include <cuda_runtime.h>
#include <cuda_bf16.h>

// out[row,:] = W[days[row],:] + b.  131072 rows, D=1024 fp32 (537MB writes).
//
// Counting-sort by day (365 bins), then a write-only main kernel:
// each CTA owns (day, split): holds W[day]+b in registers (1 float4/thread,
// 256 threads = full 4KB row) and streams full-row stores for its row subset.
// Removes the entire 537MB per-row W read stream from L1TEX/L2.

static constexpr int NDAYS  = 365;
static constexpr int NROWSMAX = 131072;
static constexpr int D4     = 256;    // 1024 floats / 4
static constexpr int NSPLIT = 16;     // row-splits per day -> grid 365*16

__device__ unsigned int g_counts[NDAYS];
__device__ unsigned int g_offsets[NDAYS + 1];
__device__ unsigned int g_cursor[NDAYS];
__device__ unsigned int g_rowlist[NROWSMAX];

// ---- (1) zero counts ----
__global__ void k_zero()
{
    if (threadIdx.x < NDAYS) g_counts[threadIdx.x] = 0;
}

// ---- (2) histogram with smem pre-aggregation ----
__global__ void __launch_bounds__(512)
k_hist(const int* __restrict__ days, int n)
{
    __shared__ unsigned int h[NDAYS];
    for (int i = threadIdx.x; i < NDAYS; i += 512) h[i] = 0;
    __syncthreads();

    const int base = blockIdx.x * 2048;
#pragma unroll
    for (int k = 0; k < 4; ++k) {
        int idx = base + k * 512 + threadIdx.x;
        if (idx < n) atomicAdd(&h[days[idx]], 1u);
    }
    __syncthreads();
    for (int i = threadIdx.x; i < NDAYS; i += 512)
        if (h[i]) atomicAdd(&g_counts[i], h[i]);
}

// ---- (3) scan (single CTA, Hillis-Steele in smem) ----
__global__ void __launch_bounds__(512)
k_scan()
{
    __shared__ unsigned int s[512];
    const int t = threadIdx.x;
    unsigned int cnt = (t < NDAYS) ? g_counts[t] : 0u;
    s[t] = cnt;
    __syncthreads();
#pragma unroll
    for (int off = 1; off < 512; off <<= 1) {
        unsigned int v = (t >= off) ? s[t - off] : 0u;
        __syncthreads();
        s[t] += v;
        __syncthreads();
    }
    if (t == 0) g_offsets[0] = 0;
    if (t < NDAYS) {
        g_offsets[t + 1] = s[t];        // inclusive
        g_cursor[t]      = s[t] - cnt;  // exclusive (scatter cursor)
    }
}

// ---- (4) scatter row ids into per-day lists (smem two-phase) ----
__global__ void __launch_bounds__(1024)
k_scatter(const int* __restrict__ days, int n)
{
    __shared__ unsigned int scnt[NDAYS];
    __shared__ unsigned int sbase[NDAYS];
    const int t = threadIdx.x;
    for (int i = t; i < NDAYS; i += 1024) scnt[i] = 0;
    __syncthreads();

    const int base = blockIdx.x * 4096;
    int d[4]; unsigned int rank[4]; int idx[4];
#pragma unroll
    for (int k = 0; k < 4; ++k) {
        idx[k] = base + k * 1024 + t;
        if (idx[k] < n) {
            d[k] = days[idx[k]];
            rank[k] = atomicAdd(&scnt[d[k]], 1u);
        } else d[k] = -1;
    }
    __syncthreads();
    for (int i = t; i < NDAYS; i += 1024)
        if (scnt[i]) sbase[i] = atomicAdd(&g_cursor[i], scnt[i]);
    __syncthreads();
#pragma unroll
    for (int k = 0; k < 4; ++k)
        if (d[k] >= 0)
            g_rowlist[sbase[d[k]] + rank[k]] = (unsigned int)idx[k];
}

// ---- (5) main: register-resident row value, write-only streaming ----
__global__ void __launch_bounds__(256)
k_main(const float4* __restrict__ W4,
       const float4* __restrict__ b4,
       float4* __restrict__ out4)
{
    const int day   = blockIdx.x % NDAYS;
    const int split = blockIdx.x / NDAYS;
    const int t     = threadIdx.x;

    float4 w = __ldg(W4 + (size_t)day * D4 + t);
    const float4 bv = __ldg(b4 + t);
    w.x += bv.x; w.y += bv.y; w.z += bv.z; w.w += bv.w;

    const unsigned int beg = g_offsets[day];
    const unsigned int end = g_offsets[day + 1];

    unsigned int i = beg + split;
    // unroll 4 for deep store MLP
    for (; i + 3u * NSPLIT < end; i += 4u * NSPLIT) {
        unsigned int r0 = g_rowlist[i];
        unsigned int r1 = g_rowlist[i + NSPLIT];
        unsigned int r2 = g_rowlist[i + 2u * NSPLIT];
        unsigned int r3 = g_rowlist[i + 3u * NSPLIT];
        __stcs(out4 + (size_t)r0 * D4 + t, w);
        __stcs(out4 + (size_t)r1 * D4 + t, w);
        __stcs(out4 + (size_t)r2 * D4 + t, w);
        __stcs(out4 + (size_t)r3 * D4 + t, w);
    }
    for (; i < end; i += NSPLIT) {
        unsigned int r = g_rowlist[i];
        __stcs(out4 + (size_t)r * D4 + t, w);
    }
}

extern "C" void kernel_launch(void* const* d_in, const int* in_sizes, int n_in,
                              void* d_out, int out_size)
{
    const int*    days = (const int*)d_in[0];
    const float4* W4   = (const float4*)d_in[1];
    const float4* b4   = (const float4*)d_in[2];
    float4*       out4 = (float4*)d_out;

    const int n = in_sizes[0];   // 131072

    k_zero<<<1, 512>>>();
    k_hist<<<(n + 2047) / 2048, 512>>>(days, n);
    k_scan<<<1, 512>>>();
    k_scatter<<<(n + 4095) / 4096, 1024>>>(days, n);
    k_main<<<NDAYS * NSPLIT, 256>>>(W4, b4, out4);
}

// round 7
// speedup vs baseline: 3.7070x; 1.6247x over previous
#include <cuda_runtime.h>
#include <cuda_bf16.h>

// out[row, :] = W[days[row], :] + bias, D = 1024 floats = 256 float4.
// R3 structure (proven 75.8us, DRAM ~80%): one CTA of 256 threads handles
// 8 rows in two pipelined batches of 4, regs<=32 so 8 CTAs/SM.
// R7 single change: default write-back stores instead of __stcs streaming —
// let L2 buffer/schedule the 537MB write stream into DRAM-friendlier bursts.
static constexpr int D4 = 256;          // 1024 / 4
static constexpr int ROWS_PER_CTA = 8;
static constexpr int BATCH = 4;

__global__ void __launch_bounds__(256, 8)
doy_gather8x4_wb_kernel(const int* __restrict__ days,
                        const float4* __restrict__ W4,
                        const float4* __restrict__ b4,
                        float4* __restrict__ out4)
{
    const int d4   = threadIdx.x;                 // column (float4 index)
    const int row0 = blockIdx.x * ROWS_PER_CTA;

    const float4 b = __ldg(b4 + d4);              // once per thread

    int day[ROWS_PER_CTA];
#pragma unroll
    for (int r = 0; r < ROWS_PER_CTA; ++r)
        day[r] = __ldg(days + row0 + r);

#pragma unroll
    for (int batch = 0; batch < ROWS_PER_CTA / BATCH; ++batch) {
        const int base = batch * BATCH;
        float4 w[BATCH];
#pragma unroll
        for (int r = 0; r < BATCH; ++r)
            w[r] = __ldg(W4 + (size_t)day[base + r] * D4 + d4);  // L2-resident table

#pragma unroll
        for (int r = 0; r < BATCH; ++r) {
            float4 v;
            v.x = w[r].x + b.x;
            v.y = w[r].y + b.y;
            v.z = w[r].z + b.z;
            v.w = w[r].w + b.w;
            out4[(size_t)(row0 + base + r) * D4 + d4] = v;   // default write-back
        }
    }
}

extern "C" void kernel_launch(void* const* d_in, const int* in_sizes, int n_in,
                              void* d_out, int out_size)
{
    const int*    days = (const int*)d_in[0];
    const float4* W4   = (const float4*)d_in[1];
    const float4* b4   = (const float4*)d_in[2];
    float4*       out4 = (float4*)d_out;

    const int n_rows = in_sizes[0];                 // B*T = 131072 (divisible by 8)
    const int n_cta  = n_rows / ROWS_PER_CTA;       // 16384

    doy_gather8x4_wb_kernel<<<n_cta, 256>>>(days, W4, b4, out4);
}